// round 8
// baseline (speedup 1.0000x reference)
#include <cuda_runtime.h>
#include <cuda_bf16.h>
#include <math.h>

// Problem constants (from reference): N_CUTS=4e6, DIM=64, N_CLUSTERS=50, N_VARIANTS=2000
#define DIM 64
#define MAX_SEG 100000
#define MAX_VD  131072   // >= n_variants * DIM = 128000  (R7 bug: was MAX_SEG)
#define MAX_CLUSTERS 64

// Scratch (static: allocation-free rule)
__device__ float g_raw[(size_t)MAX_SEG * DIM];    // raw segment sums, 25.6 MB
__device__ float g_mean[(size_t)MAX_VD];          // per-(v,d) mean
__device__ float g_idn[(size_t)MAX_VD];           // per-(v,d) 1/(std+1e-5)

// Fast log1p for |x| small (here |x| <~ 0.01 always): 5-term Taylor, error
// x^6/6 (< 3e-9 relative even at x=0.05). Guarded fallback for robustness.
__device__ __forceinline__ float log1p_fast(float x) {
    if (fabsf(x) > 0.1f) return log1pf(x);
    return x * (1.f - x * (0.5f - x * (0.33333333f - x * (0.25f - x * 0.2f))));
}

// Per-warp indptr dtype check (1 load per lane for lanes 0..15; L2-hot).
// int64 values here are << 2^31 -> all odd 32-bit words zero; int32 odd words
// are sorted random breakpoints (essentially never all zero).
__device__ __forceinline__ bool indptr_is_64_warp(const int* __restrict__ ipw, int lane) {
    int w = (lane < 16) ? __ldg(&ipw[2 * lane + 1]) : 0;
    return __ballot_sync(0xffffffffu, w != 0) == 0u;
}

// ---------------------------------------------------------------------------
// Kernel 1: CSR segment sum. One CTA per segment (block-per-segment: 100k
// small CTAs retire independently -> fine-grained load balance across the
// exponential segment-length distribution). 128 threads = 8 rows x 16 float4
// lanes; each iteration streams a contiguous 2KB block fully coalesced.
// ---------------------------------------------------------------------------
__global__ void __launch_bounds__(128) seg_sum_kernel(
    const float4* __restrict__ emb,   // [n_cuts * 16] float4 (row = 16 float4)
    const int* __restrict__ ipw,      // indptr as 32-bit words
    float* __restrict__ raw)          // [n_seg * 64]
{
    const int s = blockIdx.x;
    const int tid = threadIdx.x;
    const int lane = tid & 31;

    long long r0, r1;
    if (indptr_is_64_warp(ipw, lane)) {
        const long long* ip = (const long long*)ipw;
        r0 = __ldg(&ip[s]); r1 = __ldg(&ip[s + 1]);
    } else {
        r0 = (long long)__ldg(&ipw[s]); r1 = (long long)__ldg(&ipw[s + 1]);
    }

    const int q = tid & 15;   // float4 index within a row (0..15)
    const int g = tid >> 4;   // row group (0..7)

    float ax = 0.f, ay = 0.f, az = 0.f, aw = 0.f;
    for (long long r = r0 + g; r < r1; r += 8) {
        float4 v = __ldg(&emb[r * 16 + q]);
        ax += v.x; ay += v.y; az += v.z; aw += v.w;
    }

    __shared__ float4 sm[128];
    sm[tid] = make_float4(ax, ay, az, aw);
    __syncthreads();

    #pragma unroll
    for (int st = 64; st >= 16; st >>= 1) {
        if (tid < st) {
            float4 a = sm[tid];
            float4 b = sm[tid + st];
            sm[tid] = make_float4(a.x + b.x, a.y + b.y, a.z + b.z, a.w + b.w);
        }
        __syncthreads();
    }

    if (tid < 16) {
        ((float4*)(raw + (long long)s * DIM))[tid] = sm[tid];
    }
}

// ---------------------------------------------------------------------------
// Kernel 2a: per-(variant, dim) statistics across clusters.
//   y = log1p(raw / lib[c]) on UNSHIFTED values (shift-invariance avoids the
//   fp32 cancellation the -2 offset would cause; std ~ 6e-5 vs values ~ 2).
//   Stores mean and 1/(std+1e-5).
// ---------------------------------------------------------------------------
__global__ void __launch_bounds__(256) stats_kernel(
    const float* __restrict__ raw,   // [n_clusters * n_variants * 64]
    const float* __restrict__ lib,   // [n_clusters]
    float* __restrict__ meanv,       // [n_variants * 64]
    float* __restrict__ idnv,        // [n_variants * 64]
    int n_clusters, int n_variants)
{
    __shared__ float s_inv[MAX_CLUSTERS];
    if (threadIdx.x < n_clusters) s_inv[threadIdx.x] = 1.f / lib[threadIdx.x];
    __syncthreads();

    const int idx = blockIdx.x * blockDim.x + threadIdx.x; // v*64 + d
    const int total = n_variants * DIM;
    if (idx >= total) return;

    const int cstride = n_variants * DIM;
    const float* p = raw + idx;

    float sum = 0.f, ssq = 0.f;
    #pragma unroll 5
    for (int c = 0; c < n_clusters; ++c) {
        float y = log1p_fast(__ldg(p) * s_inv[c]);
        p += cstride;
        sum += y;
        ssq = fmaf(y, y, ssq);
    }

    const float meanY = sum / (float)n_clusters;
    const float var = (ssq - sum * meanY) / (float)(n_clusters - 1);
    const float stdv = sqrtf(fmaxf(var, 0.f));
    meanv[idx] = meanY;
    idnv[idx]  = 1.f / (stdv + 1e-5f);
}

// ---------------------------------------------------------------------------
// Kernel 2b: apply. One thread per (c, v, float4-of-dims): 1.6M threads.
//   out[c,v,:64] = y - 2 ; out[c,v,64:] = (y - mean)*idn
// raw/mean/idn reads are L2-hot (27 MB total); output 51.2 MB is the only
// DRAM stream -> near store-bandwidth floor.
// ---------------------------------------------------------------------------
__global__ void __launch_bounds__(256) apply_kernel(
    const float4* __restrict__ raw,   // [n_clusters * n_variants * 16] float4
    const float* __restrict__ lib,    // [n_clusters]
    const float4* __restrict__ meanv, // [n_variants * 16] float4
    const float4* __restrict__ idnv,  // [n_variants * 16] float4
    float4* __restrict__ out,         // [n_clusters * n_variants * 32] float4
    int n_clusters, int n_variants)
{
    const int idx = blockIdx.x * blockDim.x + threadIdx.x; // (c*nv + v)*16 + q
    const int total = n_clusters * n_variants * 16;
    if (idx >= total) return;

    const int q  = idx & 15;
    const int cv = idx >> 4;          // c*nv + v
    const int c  = cv / n_variants;
    const int v  = cv - c * n_variants;

    const float inv = 1.f / __ldg(&lib[c]);
    float4 r = __ldg(&raw[idx]);
    float4 m = __ldg(&meanv[v * 16 + q]);
    float4 i = __ldg(&idnv[v * 16 + q]);

    float4 y;
    y.x = log1p_fast(r.x * inv);
    y.y = log1p_fast(r.y * inv);
    y.z = log1p_fast(r.z * inv);
    y.w = log1p_fast(r.w * inv);

    const int o = cv * 32;
    out[o + q]      = make_float4(y.x - 2.f, y.y - 2.f, y.z - 2.f, y.w - 2.f);
    out[o + 16 + q] = make_float4((y.x - m.x) * i.x, (y.y - m.y) * i.y,
                                  (y.z - m.z) * i.z, (y.w - m.w) * i.w);
}

extern "C" void kernel_launch(void* const* d_in, const int* in_sizes, int n_in,
                              void* d_out, int out_size)
{
    const float* emb    = (const float*)d_in[0];   // [n_cuts, 64] fp32
    const float* lib    = (const float*)d_in[1];   // [n_clusters] fp32
    const int*   indptr = (const int*)d_in[2];     // [n_seg + 1] int32 OR int64 words

    const int n_clusters = in_sizes[1];
    const int n_seg      = in_sizes[2] - 1;
    const int n_variants = n_seg / n_clusters;

    float *raw, *meanv, *idnv;
    cudaGetSymbolAddress((void**)&raw, g_raw);
    cudaGetSymbolAddress((void**)&meanv, g_mean);
    cudaGetSymbolAddress((void**)&idnv, g_idn);

    // Kernel 1: one block per segment
    seg_sum_kernel<<<n_seg, 128>>>((const float4*)emb, indptr, raw);

    // Kernel 2a: stats per (variant, dim)
    const int total_vd = n_variants * DIM;
    stats_kernel<<<(total_vd + 255) / 256, 256>>>(raw, lib, meanv, idnv,
                                                  n_clusters, n_variants);

    // Kernel 2b: apply per (cluster, variant, dim4)
    const int total_ap = n_clusters * n_variants * 16;
    apply_kernel<<<(total_ap + 255) / 256, 256>>>(
        (const float4*)raw, lib, (const float4*)meanv, (const float4*)idnv,
        (float4*)d_out, n_clusters, n_variants);
}

// round 9
// speedup vs baseline: 1.1008x; 1.1008x over previous
#include <cuda_runtime.h>
#include <cuda_bf16.h>
#include <math.h>

// Problem constants (from reference): N_CUTS=4e6, DIM=64, N_CLUSTERS=50, N_VARIANTS=2000
#define DIM 64
#define MAX_SEG 100000
#define MAX_VD  131072   // >= n_variants * DIM = 128000
#define MAX_CLUSTERS 64

// Scratch (static: allocation-free rule)
__device__ float g_raw[(size_t)MAX_SEG * DIM];    // raw segment sums, 25.6 MB
__device__ float g_mean[(size_t)MAX_VD];          // per-(v,d) mean
__device__ float g_idn[(size_t)MAX_VD];           // per-(v,d) 1/(std+1e-5)

// Fast log1p for |x| small (here |x| <~ 0.01 always): 5-term Taylor, error
// x^6/6 (< 3e-9 relative even at x=0.05). Guarded fallback for robustness.
__device__ __forceinline__ float log1p_fast(float x) {
    if (fabsf(x) > 0.1f) return log1pf(x);
    return x * (1.f - x * (0.5f - x * (0.33333333f - x * (0.25f - x * 0.2f))));
}

// Per-warp indptr dtype check (1 load per lane for lanes 0..15; L2-hot).
// int64 values here are << 2^31 -> all odd 32-bit words zero; int32 odd words
// are sorted random breakpoints (essentially never all zero).
__device__ __forceinline__ bool indptr_is_64_warp(const int* __restrict__ ipw, int lane) {
    int w = (lane < 16) ? __ldg(&ipw[2 * lane + 1]) : 0;
    return __ballot_sync(0xffffffffu, w != 0) == 0u;
}

// ---------------------------------------------------------------------------
// Kernel 1: CSR segment sum. One CTA per segment. 128 threads = 8 row-groups
// x 16 float4 lanes; each iteration streams a contiguous 2KB block.
// 32-bit trip counter + pointer increment (no 64-bit IMAD chain per iter).
// Reduction: shfl-combine halves within each warp, then ONE __syncthreads and
// a 4-way smem add by warp 0 (was a 4-sync tree).
// ---------------------------------------------------------------------------
__global__ void __launch_bounds__(128) seg_sum_kernel(
    const float4* __restrict__ emb,   // [n_cuts * 16] float4 (row = 16 float4)
    const int* __restrict__ ipw,      // indptr as 32-bit words
    float* __restrict__ raw)          // [n_seg * 64]
{
    const int s = blockIdx.x;
    const int tid = threadIdx.x;
    const int lane = tid & 31;

    int r0, r1;  // row indices < 4M: always fit in int32
    if (indptr_is_64_warp(ipw, lane)) {
        const long long* ip = (const long long*)ipw;
        r0 = (int)__ldg(&ip[s]); r1 = (int)__ldg(&ip[s + 1]);
    } else {
        r0 = __ldg(&ipw[s]); r1 = __ldg(&ipw[s + 1]);
    }

    const int q = tid & 15;   // float4 index within a row (0..15)
    const int g = tid >> 4;   // row group (0..7)

    float ax = 0.f, ay = 0.f, az = 0.f, aw = 0.f;
    {
        const float4* p = emb + (size_t)(r0 + g) * 16 + q;
        int n = r1 - (r0 + g);            // remaining rows for this group
        for (; n > 0; n -= 8, p += 128) { // stride 8 rows = 2KB
            float4 v = __ldg(p);
            ax += v.x; ay += v.y; az += v.z; aw += v.w;
        }
    }

    // combine the two row-halves inside each warp (lanes 0-15 keep result)
    ax += __shfl_down_sync(0xffffffffu, ax, 16);
    ay += __shfl_down_sync(0xffffffffu, ay, 16);
    az += __shfl_down_sync(0xffffffffu, az, 16);
    aw += __shfl_down_sync(0xffffffffu, aw, 16);

    __shared__ float4 sm[4][16];
    const int w = tid >> 5;
    if (lane < 16) sm[w][lane] = make_float4(ax, ay, az, aw);
    __syncthreads();

    if (tid < 16) {
        float4 a = sm[0][tid], b = sm[1][tid], c = sm[2][tid], d = sm[3][tid];
        float4 r = make_float4(a.x + b.x + c.x + d.x,
                               a.y + b.y + c.y + d.y,
                               a.z + b.z + c.z + d.z,
                               a.w + b.w + c.w + d.w);
        ((float4*)(raw + (size_t)s * DIM))[tid] = r;
    }
}

// ---------------------------------------------------------------------------
// Kernel 2a: per-(variant, dim) statistics across clusters.
//   y = log1p(raw / lib[c]) on UNSHIFTED values (shift-invariance avoids the
//   fp32 cancellation the -2 offset would cause; std ~ 6e-5 vs values ~ 2).
// ---------------------------------------------------------------------------
__global__ void __launch_bounds__(256) stats_kernel(
    const float* __restrict__ raw,   // [n_clusters * n_variants * 64]
    const float* __restrict__ lib,   // [n_clusters]
    float* __restrict__ meanv,       // [n_variants * 64]
    float* __restrict__ idnv,        // [n_variants * 64]
    int n_clusters, int n_variants)
{
    __shared__ float s_inv[MAX_CLUSTERS];
    if (threadIdx.x < n_clusters) s_inv[threadIdx.x] = 1.f / lib[threadIdx.x];
    __syncthreads();

    const int idx = blockIdx.x * blockDim.x + threadIdx.x; // v*64 + d
    const int total = n_variants * DIM;
    if (idx >= total) return;

    const int cstride = n_variants * DIM;
    const float* p = raw + idx;

    float sum = 0.f, ssq = 0.f;
    #pragma unroll 5
    for (int c = 0; c < n_clusters; ++c) {
        float y = log1p_fast(__ldg(p) * s_inv[c]);
        p += cstride;
        sum += y;
        ssq = fmaf(y, y, ssq);
    }

    const float meanY = sum / (float)n_clusters;
    const float var = (ssq - sum * meanY) / (float)(n_clusters - 1);
    const float stdv = sqrtf(fmaxf(var, 0.f));
    meanv[idx] = meanY;
    idnv[idx]  = 1.f / (stdv + 1e-5f);
}

// ---------------------------------------------------------------------------
// Kernel 2b: apply. 2D grid: blockIdx.y = cluster (kills the per-thread int
// division of R8), one RCP per block via smem (kills 1.6M MUFU.RCP).
// Thread i covers (v,q) = (i>>4, i&15); out offset = c*nv*32 + 2i - (i&15).
// ---------------------------------------------------------------------------
__global__ void __launch_bounds__(256) apply_kernel(
    const float4* __restrict__ raw,   // [n_clusters * n_variants * 16] float4
    const float* __restrict__ lib,    // [n_clusters]
    const float4* __restrict__ meanv, // [n_variants * 16] float4
    const float4* __restrict__ idnv,  // [n_variants * 16] float4
    float4* __restrict__ out,         // [n_clusters * n_variants * 32] float4
    int n_variants)
{
    const int c = blockIdx.y;
    __shared__ float s_inv;
    if (threadIdx.x == 0) s_inv = 1.f / __ldg(&lib[c]);
    __syncthreads();

    const int i = blockIdx.x * blockDim.x + threadIdx.x; // v*16 + q
    const int total = n_variants * 16;
    if (i >= total) return;

    const float inv = s_inv;
    float4 r = __ldg(&raw[(size_t)c * total + i]);
    float4 m = __ldg(&meanv[i]);
    float4 d = __ldg(&idnv[i]);

    float4 y;
    y.x = log1p_fast(r.x * inv);
    y.y = log1p_fast(r.y * inv);
    y.z = log1p_fast(r.z * inv);
    y.w = log1p_fast(r.w * inv);

    const size_t o = (size_t)c * (n_variants * 32) + 2 * i - (i & 15);
    out[o]      = make_float4(y.x - 2.f, y.y - 2.f, y.z - 2.f, y.w - 2.f);
    out[o + 16] = make_float4((y.x - m.x) * d.x, (y.y - m.y) * d.y,
                              (y.z - m.z) * d.z, (y.w - m.w) * d.w);
}

extern "C" void kernel_launch(void* const* d_in, const int* in_sizes, int n_in,
                              void* d_out, int out_size)
{
    const float* emb    = (const float*)d_in[0];   // [n_cuts, 64] fp32
    const float* lib    = (const float*)d_in[1];   // [n_clusters] fp32
    const int*   indptr = (const int*)d_in[2];     // [n_seg + 1] int32 OR int64 words

    const int n_clusters = in_sizes[1];
    const int n_seg      = in_sizes[2] - 1;
    const int n_variants = n_seg / n_clusters;

    float *raw, *meanv, *idnv;
    cudaGetSymbolAddress((void**)&raw, g_raw);
    cudaGetSymbolAddress((void**)&meanv, g_mean);
    cudaGetSymbolAddress((void**)&idnv, g_idn);

    // Kernel 1: one block per segment
    seg_sum_kernel<<<n_seg, 128>>>((const float4*)emb, indptr, raw);

    // Kernel 2a: stats per (variant, dim)
    const int total_vd = n_variants * DIM;
    stats_kernel<<<(total_vd + 255) / 256, 256>>>(raw, lib, meanv, idnv,
                                                  n_clusters, n_variants);

    // Kernel 2b: apply, 2D grid (x: variant*dim4, y: cluster)
    const int total_i = n_variants * 16;
    dim3 grid2((total_i + 255) / 256, n_clusters);
    apply_kernel<<<grid2, 256>>>(
        (const float4*)raw, lib, (const float4*)meanv, (const float4*)idnv,
        (float4*)d_out, n_variants);
}